// round 17
// baseline (speedup 1.0000x reference)
#include <cuda_runtime.h>
#include <cuda_fp16.h>
#include <cstdint>

// DepthConv: out[b,o,p] = sum_t gate[b,t,p] * sum_c w[t,o,c]*x[b,c,p+shift(t)]
// R7 champion hot loop, with the x fp32->fp16 conversion FUSED into the
// pipeline: fp32 halo staged via cp.async in 16-channel quarters (double-
// buffered F strip), converted smem->smem into the fp16 halo two iterations
// later, in the post-compute shadow. No x prepass; weights-only prep kernel.

#define ALPHA_F 8.3f

constexpr int Bn = 8;
constexpr int Cn = 512;
constexpr int Hn = 64;
constexpr int Wn = 64;
constexpr int On = 64;
constexpr int PIXn = Hn * Wn;       // 4096

constexpr int Mt = 128;             // pixels per CTA (8 rows x 16 cols)
constexpr int KC = 64;              // c-chunk per epoch
constexpr int EPOCHS = Cn / KC;     // 8
constexpr int NIT = EPOCHS * 9;     // 72 (epoch-major, tap-minor)
constexpr int HE = 180;             // halo entries (10 x 18)
constexpr int HS = 72;              // halo row stride in halves (64 + 8 pad)
constexpr int FPIX = 24;            // F strip pixels per row (6 x 4, aligned)
constexpr int FCH = 16;             // F strip channels (quarter of KC)
constexpr int FBUF = FCH * 10 * FPIX * 4;   // 15360 bytes per F buffer

// ---- device-global scratch (weights only) ----
__device__ __half g_wh[9 * On * Cn];              // [tap][o][c]  fp16

// ---- smem layout (bytes) ----
constexpr int HBUF = HE * HS * 2;            // 25920 (x2 buffers)
constexpr int BBUF = On * HS * 2;            // 9216  (x3 buffers)
constexpr int OFF_H = 0;
constexpr int OFF_B = 2 * HBUF;              // 51840
constexpr int OFF_F = OFF_B + 3 * BBUF;      // 79488 (2 x 15360)
constexpr int OFF_G = OFF_F + 2 * FBUF;      // 110208 gates 9*128*4
constexpr int SMEM_TOTAL = OFF_G + 9 * Mt * 4;  // 114816 -> 2 CTAs/SM

// ====================== helpers ======================
__device__ __forceinline__ uint32_t smem_u32(const void* p) {
    uint32_t a;
    asm("{ .reg .u64 t; cvta.to.shared.u64 t, %1; cvt.u32.u64 %0, t; }"
        : "=r"(a) : "l"(p));
    return a;
}
__device__ __forceinline__ void ldsm_x4(uint32_t* r, uint32_t addr) {
    asm volatile("ldmatrix.sync.aligned.m8n8.x4.shared.b16 {%0,%1,%2,%3}, [%4];"
        : "=r"(r[0]), "=r"(r[1]), "=r"(r[2]), "=r"(r[3]) : "r"(addr));
}
__device__ __forceinline__ void mma16816(float* c, const uint32_t* a,
                                         uint32_t b0, uint32_t b1) {
    asm volatile(
        "mma.sync.aligned.m16n8k16.row.col.f32.f16.f16.f32 "
        "{%0,%1,%2,%3}, {%4,%5,%6,%7}, {%8,%9}, {%0,%1,%2,%3};"
        : "+f"(c[0]), "+f"(c[1]), "+f"(c[2]), "+f"(c[3])
        : "r"(a[0]), "r"(a[1]), "r"(a[2]), "r"(a[3]), "r"(b0), "r"(b1));
}
__device__ __forceinline__ uint32_t hmul2u(uint32_t a, uint32_t g) {
    __half2 r = __hmul2(*reinterpret_cast<__half2*>(&a),
                        *reinterpret_cast<__half2*>(&g));
    return *reinterpret_cast<uint32_t*>(&r);
}
#define CP_ASYNC16(dst, src) \
    asm volatile("cp.async.cg.shared.global [%0], [%1], 16;" \
                 :: "r"(dst), "l"(src) : "memory")
#define CP_COMMIT() asm volatile("cp.async.commit_group;" ::: "memory")
#define CP_WAIT1()  asm volatile("cp.async.wait_group 1;" ::: "memory")
#define CP_WAIT0()  asm volatile("cp.async.wait_group 0;" ::: "memory")

// ====================== weight pre-pass (tiny) ======================
constexpr int NW_ELEM = 9 * On * Cn;                   // 294912
constexpr int NW_BLK = NW_ELEM / (256 * 8);            // 144

__global__ __launch_bounds__(256) void prep_w(const float* __restrict__ w) {
    const int base = blockIdx.x * 2048 + threadIdx.x;
    #pragma unroll
    for (int j = 0; j < 8; j++) {
        const int idx = base + j * 256;          // [t][o][c]
        const int c = idx % Cn;
        const int o = (idx / Cn) % On;
        const int t = idx / (Cn * On);
        g_wh[idx] = __float2half_rn(w[((size_t)o * Cn + c) * 9 + t]);
    }
}

// ====================== main kernel ======================
__global__ __launch_bounds__(256, 2) void depthconv_mma(
    const float* __restrict__ xg,
    const float* __restrict__ depth,
    float* __restrict__ out)
{
    extern __shared__ __align__(16) char smem[];
    const uint32_t sb = smem_u32(smem);
    uint32_t* g_sp = reinterpret_cast<uint32_t*>(smem + OFF_G);  // [9][128] half2

    const int tid = threadIdx.x;
    const int wid = tid >> 5;
    const int lid = tid & 31;

    const int blk = blockIdx.x;          // 0..255
    const int b   = blk >> 5;
    const int tl  = blk & 31;
    const int h0  = (tl >> 2) * 8;       // 8 pixel rows
    const int w0  = (tl & 3) * 16;       // 16 pixel cols

    // ---- gates: 9 taps x 128 pixels, stored as (g,g) half2 ----
    if (tid < Mt) {
        const int hh = h0 + (tid >> 4);
        const int ww = w0 + (tid & 15);
        const float* dptr = depth + b * PIXn;
        const float d0 = dptr[hh * Wn + ww];
        #pragma unroll
        for (int t = 0; t < 9; t++) {
            const int h2 = hh + t / 3 - 1, w2 = ww + t % 3 - 1;
            float g = 0.f;
            if (h2 >= 0 && h2 < Hn && w2 >= 0 && w2 < Wn)
                g = __expf(-ALPHA_F * fabsf(d0 - dptr[h2 * Wn + w2]));
            const __half gh = __float2half_rn(g);
            __half2 gp = __halves2half2(gh, gh);
            g_sp[t * Mt + tid] = *reinterpret_cast<uint32_t*>(&gp);
        }
    }

    // ---- F (fp32 halo quarter) staging slots: 960 16B chunks / 256 thr ----
    const float* xb = xg + (size_t)b * Cn * PIXn;
    int      fgoff[4];    // x float offset (add channel-quarter base)
    uint32_t fsoff[4];    // byte offset within one F buffer
    const int nfk = (tid < 192) ? 4 : 3;
    #pragma unroll
    for (int k = 0; k < 4; k++) {
        const int i = tid + k * 256;
        if (k < nfk) {
            const int c16 = i / 60;
            const int rem = i - c16 * 60;
            const int hr  = rem / 6;
            const int j   = rem - hr * 6;
            const int hh  = min(max(h0 - 1 + hr, 0), Hn - 1);
            const int wj  = min(max(w0 - 4 + 4 * j, 0), Wn - 4);
            fgoff[k] = c16 * PIXn + hh * Wn + wj;
            fsoff[k] = (uint32_t)((c16 * 10 * FPIX + hr * FPIX + j * 4) * 4);
        } else { fgoff[k] = 0; fsoff[k] = 0; }
    }
    // stage quarter q of epoch e1 into F buffer (q&1)
    auto stage_Fq = [&](int e1, int q) {
        const int cbase = (e1 * KC + q * FCH) * PIXn;
        const uint32_t fd = sb + OFF_F + (uint32_t)(q & 1) * FBUF;
        #pragma unroll
        for (int k = 0; k < 4; k++)
            if (k < nfk)
                CP_ASYNC16(fd + fsoff[k], (const char*)(xb + cbase + fgoff[k]));
    };

    // ---- convert slots: 360 (ent, 8ch) units / 256 thr ----
    uint32_t cvF[2];      // F float offset of channel-group column
    uint32_t cvH[2];      // halo half offset (add q*16 cols + buf)
    const int nck = (tid < 104) ? 2 : 1;
    #pragma unroll
    for (int k = 0; k < 2; k++) {
        const int u = tid + k * 256;
        if (k < nck) {
            const int ent = u >> 1;
            const int g8  = u & 1;
            const int hr  = ent / 18;
            const int hc  = ent - hr * 18;
            cvF[k] = (uint32_t)(g8 * 8 * 10 * FPIX + hr * FPIX + hc + 3);
            cvH[k] = (uint32_t)(ent * HS + g8 * 8);
        } else { cvF[k] = 0; cvH[k] = 0; }
    }
    // convert quarter q (already in F buffer q&1) into halo buf (e1&1)
    auto convert_q = [&](int e1, int q) {
        const float* F = reinterpret_cast<const float*>(
            smem + OFF_F + (q & 1) * FBUF);
        char* hb = smem + OFF_H + (e1 & 1) * HBUF;
        #pragma unroll
        for (int k = 0; k < 2; k++) {
            if (k >= nck) continue;
            const float* src = F + cvF[k];
            float f0 = src[0 * 10 * FPIX], f1 = src[1 * 10 * FPIX];
            float f2 = src[2 * 10 * FPIX], f3 = src[3 * 10 * FPIX];
            float f4 = src[4 * 10 * FPIX], f5 = src[5 * 10 * FPIX];
            float f6 = src[6 * 10 * FPIX], f7 = src[7 * 10 * FPIX];
            __half2 h01 = __floats2half2_rn(f0, f1);
            __half2 h23 = __floats2half2_rn(f2, f3);
            __half2 h45 = __floats2half2_rn(f4, f5);
            __half2 h67 = __floats2half2_rn(f6, f7);
            uint4 v;
            v.x = *reinterpret_cast<uint32_t*>(&h01);
            v.y = *reinterpret_cast<uint32_t*>(&h23);
            v.z = *reinterpret_cast<uint32_t*>(&h45);
            v.w = *reinterpret_cast<uint32_t*>(&h67);
            *reinterpret_cast<uint4*>(hb + (cvH[k] + q * FCH) * 2) = v;
        }
    };

    // ---- B staging: 512 chunks -> 2 per thread ----
    uint32_t bsoff[2];
    int boff[2];
    #pragma unroll
    for (int j = 0; j < 2; j++) {
        const int i = tid + j * 256;
        const int o = i >> 3, seg = i & 7;
        boff[j]  = o * Cn + seg * 8;
        bsoff[j] = (uint32_t)(o * HS + seg * 8) * 2;
    }
    auto stage_B = [&](int it, int buf) {
        const int e = it / 9, t = it - e * 9;
        const uint32_t bd = sb + OFF_B + buf * BBUF;
        const __half* wsrc = g_wh + (size_t)t * On * Cn + e * KC;
        #pragma unroll
        for (int j = 0; j < 2; j++)
            CP_ASYNC16(bd + bsoff[j], (const char*)(wsrc + boff[j]));
    };

    // ---- warp tiling: 4 (m) x 2 (n) warps; warp tile 32x32 ----
    const int wm = (wid & 3) * 32;
    const int wn = (wid >> 2) * 32;

    uint32_t abase[2];                    // per-lane A ldmatrix base (tap 0)
    #pragma unroll
    for (int mb = 0; mb < 2; mb++) {
        const int m   = wm + mb * 16 + (lid & 15);
        const int ent = (m >> 4) * 18 + (m & 15);
        abase[mb] = sb + OFF_H + (uint32_t)(ent * HS) * 2 + (uint32_t)(lid >> 4) * 16;
    }
    uint32_t bbase[2];                    // per-lane B ldmatrix base
    {
        const int br = (lid & 7) + ((lid >> 4) << 3);
        const uint32_t bcol = (uint32_t)(((lid >> 3) & 1) << 3) * 2;
        #pragma unroll
        for (int np = 0; np < 2; np++)
            bbase[np] = sb + OFF_B + (uint32_t)((wn + np * 16 + br) * HS) * 2 + bcol;
    }
    const int grow = (lid >> 2);          // gate row within warp m-block

    float facc[2][4][4];
    #pragma unroll
    for (int i = 0; i < 2; i++)
        #pragma unroll
        for (int j = 0; j < 4; j++)
            #pragma unroll
            for (int k = 0; k < 4; k++) facc[i][j][k] = 0.f;

    // ---- prologue: build epoch-0 halo via F pipeline, then B(0), B(1) ----
    stage_Fq(0, 0); stage_Fq(0, 1); CP_COMMIT();
    CP_WAIT0(); __syncthreads();
    convert_q(0, 0); convert_q(0, 1);
    __syncthreads();                 // converts done before F buffers reused
    stage_Fq(0, 2); stage_Fq(0, 3); CP_COMMIT();
    CP_WAIT0(); __syncthreads();
    convert_q(0, 2); convert_q(0, 3);
    stage_B(0, 0); CP_COMMIT();
    stage_B(1, 1); CP_COMMIT();
    __syncthreads();                 // halo(0) + gates visible to all

    for (int it = 0; it < NIT; it++) {
        const int e = it / 9, t = it - e * 9;

        if (it >= NIT - 2) { CP_WAIT0(); } else { CP_WAIT1(); }
        __syncthreads();

        const int trow = t / 3, tcol = t - trow * 3;
        const uint32_t aoff = (uint32_t)(e & 1) * HBUF
                            + (uint32_t)((trow * 18 + tcol) * (HS * 2));
        const uint32_t boffb = (uint32_t)(it % 3) * BBUF;

        uint32_t g0[2], g1[2];            // (g,g) half2 per fragment row
        #pragma unroll
        for (int mb = 0; mb < 2; mb++) {
            const int r = wm + mb * 16 + grow;
            g0[mb] = g_sp[t * Mt + r];
            g1[mb] = g_sp[t * Mt + r + 8];
        }

        #pragma unroll
        for (int ks = 0; ks < 4; ks++) {
            uint32_t af[2][4];
            #pragma unroll
            for (int mb = 0; mb < 2; mb++) {
                ldsm_x4(af[mb], abase[mb] + aoff + ks * 32);
                af[mb][0] = hmul2u(af[mb][0], g0[mb]);
                af[mb][1] = hmul2u(af[mb][1], g1[mb]);
                af[mb][2] = hmul2u(af[mb][2], g0[mb]);
                af[mb][3] = hmul2u(af[mb][3], g1[mb]);
            }
            uint32_t bf[2][4];
            #pragma unroll
            for (int np = 0; np < 2; np++)
                ldsm_x4(bf[np], bbase[np] + boffb + ks * 32);
            #pragma unroll
            for (int mb = 0; mb < 2; mb++)
                #pragma unroll
                for (int nb = 0; nb < 4; nb++)
                    mma16816(facc[mb][nb], af[mb],
                             bf[nb >> 1][(nb & 1) * 2],
                             bf[nb >> 1][(nb & 1) * 2 + 1]);
        }

        // ---- post-compute: spread staging + deferred converts ----
        if (it + 2 < NIT) {
            stage_B(it + 2, (it + 2) % 3);
            if (e + 1 < EPOCHS && (t & 1) == 0 && t <= 6)
                stage_Fq(e + 1, t >> 1);          // q at t=0,2,4,6
            CP_COMMIT();
        }
        if (e + 1 < EPOCHS && (t & 1) == 0 && t >= 2)
            convert_q(e + 1, (t >> 1) - 1);       // q at t=2,4,6,8
    }

    // ---- epilogue: D(m=pixel, n=o) -> out[b][o][h][w] ----
    float* ob = out + (size_t)b * On * PIXn;
    const int mrow = wm + (lid >> 2);
    const int ncol = wn + (lid & 3) * 2;
    #pragma unroll
    for (int mb = 0; mb < 2; mb++) {
        #pragma unroll
        for (int half_ = 0; half_ < 2; half_++) {
            const int m  = mrow + mb * 16 + half_ * 8;
            const int hh = h0 + (m >> 4);
            const int ww = w0 + (m & 15);
            const int pix = hh * Wn + ww;
            #pragma unroll
            for (int nb = 0; nb < 4; nb++) {
                const int o = ncol + nb * 8;
                ob[(size_t)o * PIXn + pix]       = facc[mb][nb][half_ * 2];
                ob[(size_t)(o + 1) * PIXn + pix] = facc[mb][nb][half_ * 2 + 1];
            }
        }
    }
}

// ====================== launch ======================
extern "C" void kernel_launch(void* const* d_in, const int* in_sizes, int n_in,
                              void* d_out, int out_size) {
    const float* x     = (const float*)d_in[0];   // (8,512,64,64)
    const float* depth = (const float*)d_in[1];   // (8,1,64,64)
    const float* w     = (const float*)d_in[2];   // (64,512,3,3)
    float* out = (float*)d_out;                   // (8,64,64,64)

    cudaFuncSetAttribute(depthconv_mma,
                         cudaFuncAttributeMaxDynamicSharedMemorySize,
                         SMEM_TOTAL);

    prep_w<<<NW_BLK, 256>>>(w);
    depthconv_mma<<<Bn * 32, 256, SMEM_TOTAL>>>(x, depth, out);
}